// round 10
// baseline (speedup 1.0000x reference)
#include <cuda_runtime.h>
#include <cuda_fp16.h>
#include <cstdint>

// ======================= problem constants =======================
// B=128, T=1024, M=512 (GEMM N), P=256, K=512, rows = B*T = 131072
static constexpr int NB      = 128;
static constexpr int TLEN    = 1024;
static constexpr int MDIM    = 512;    // N of GEMM
static constexpr int KDIM    = 512;    // inner dim
static constexpr int MTILE   = 128;    // rows per CTA
static constexpr int NCHUNK  = 256;    // N per chunk (acc-resident)
static constexpr int NCHUNKS = MDIM / NCHUNK;    // 2
static constexpr int KSEG    = 32;     // K per B buffer / A slice
static constexpr int KSEGS   = KDIM / KSEG;      // 16
static constexpr int NITER   = NCHUNKS * KSEGS;  // 32
static constexpr int NSUPER  = NITER / 2;        // 16 (2 iters per barrier)

// padded strides (halves): rotate bank groups -> conflict-free ldmatrix
static constexpr int APAD  = 520;      // 1040 B/row
static constexpr int BPAD  = 40;       // 80 B/row (32k*2B + 16B pad)

static constexpr int SMEM_A_BYTES    = MTILE * APAD * 2;     // 133120
static constexpr int SMEM_BBUF_BYTES = NCHUNK * BPAD * 2;    // 20480
static constexpr int NBUF = 4;
static constexpr int DYN_SMEM = SMEM_A_BYTES + NBUF * SMEM_BBUF_BYTES;  // 215040

// ======================= scratch (device globals; no allocs) =======================
__device__ float g_Qt[KDIM * NB];                    // Q transposed [c][b]
__device__ float g_wq[NB * MDIM];                    // wq[b][n]
__device__ __align__(16) __half g_U16[MDIM * KDIM];  // U_d fp16 [n][k]

// ======================= helpers =======================
__device__ __forceinline__ uint32_t smem_u32(const void* p) {
    return (uint32_t)__cvta_generic_to_shared(p);
}
__device__ __forceinline__ uint32_t pack_h2(float a, float b) {
    __half2 h = __floats2half2_rn(a, b);
    return *reinterpret_cast<uint32_t*>(&h);
}
__device__ __forceinline__ void ldsm_x4(uint32_t addr, uint32_t& r0, uint32_t& r1,
                                        uint32_t& r2, uint32_t& r3) {
    asm volatile("ldmatrix.sync.aligned.m8n8.x4.shared.b16 {%0,%1,%2,%3}, [%4];"
                 : "=r"(r0), "=r"(r1), "=r"(r2), "=r"(r3) : "r"(addr));
}
__device__ __forceinline__ void mma16816(float* c, const uint32_t* a,
                                         uint32_t b0, uint32_t b1) {
    asm volatile(
        "mma.sync.aligned.m16n8k16.row.col.f32.f16.f16.f32 "
        "{%0,%1,%2,%3}, {%4,%5,%6,%7}, {%8,%9}, {%0,%1,%2,%3};"
        : "+f"(c[0]), "+f"(c[1]), "+f"(c[2]), "+f"(c[3])
        : "r"(a[0]), "r"(a[1]), "r"(a[2]), "r"(a[3]), "r"(b0), "r"(b1));
}
__device__ __forceinline__ void cp_async16(uint32_t dst, const void* src) {
    asm volatile("cp.async.cg.shared.global [%0], [%1], 16;" :: "r"(dst), "l"(src));
}
__device__ __forceinline__ void cp_commit() {
    asm volatile("cp.async.commit_group;" ::: "memory");
}
__device__ __forceinline__ void cp_wait0() {
    asm volatile("cp.async.wait_group 0;" ::: "memory");
}
// tanh(x) = 1 - 2/(e^{2x}+1): 2 MUFU, rel err ~1e-6
__device__ __forceinline__ float fast_tanh(float x) {
    float e = __expf(x + x);
    return 1.0f - __fdividef(2.0f, e + 1.0f);
}

// ======================= kernel 1: pack Qt + U -> fp16 =======================
__global__ void __launch_bounds__(256, 1) pack_kernel(const float* __restrict__ dt,
                                                      const float* __restrict__ st,
                                                      const float* __restrict__ Ud) {
    int tid = blockIdx.x * blockDim.x + threadIdx.x;
    int stride = gridDim.x * blockDim.x;
    for (int i = tid; i < KDIM * NB; i += stride) {
        int c = i >> 7, b = i & (NB - 1);
        float v = (c < 256) ? dt[b * 256 + c] : st[b * 256 + (c - 256)];
        g_Qt[c * NB + b] = v;
    }
    for (int i = tid; i < MDIM * KDIM; i += stride)
        g_U16[i] = __float2half_rn(Ud[i]);
}

// ======================= kernel 2: wq[b][n] = sum_c q[b][c]*W_d[n][c] =======================
__global__ void __launch_bounds__(128, 1) wq_kernel(const float* __restrict__ Wd) {
    __shared__ float Ws[8 * KDIM];
    int nbase = blockIdx.x * 8;
    for (int i = threadIdx.x; i < 8 * KDIM; i += 128)
        Ws[i] = Wd[nbase * KDIM + i];
    __syncthreads();
    int b = threadIdx.x;
    float acc[8];
#pragma unroll
    for (int j = 0; j < 8; j++) acc[j] = 0.0f;
    for (int c = 0; c < KDIM; c++) {
        float qv = g_Qt[c * NB + b];
#pragma unroll
        for (int j = 0; j < 8; j++) acc[j] = fmaf(qv, Ws[j * KDIM + c], acc[j]);
    }
#pragma unroll
    for (int j = 0; j < 8; j++) g_wq[b * MDIM + nbase + j] = acc[j];
}

// ======================= dummy kernel: ncu slot steering =======================
__global__ void dummy_kernel() {}

// ======================= kernel 3: fused GEMM(HMMA) + tanh + v-dot =======================
// grid = 1024 CTAs (128 rows each), 512 threads (16 warps), 1 CTA/SM.
// warp w: rowgrp = w>>2 (32 rows), ngrp = w&3 (64 n within a 256-n chunk)
// ONE barrier per 2 iterations (super-iteration); 4-buffer B ring.
__global__ void __launch_bounds__(512, 1) attn_gemm_kernel(const float* __restrict__ H,
                                                           const float* __restrict__ vd,
                                                           float* __restrict__ out) {
    extern __shared__ __align__(16) char dsm[];
    __half* smemA = reinterpret_cast<__half*>(dsm);
    char*   smemB = dsm + SMEM_A_BYTES;

    __shared__ float wq_s[MDIM];
    __shared__ float v_s[MDIM];
    __shared__ float score4[4][MTILE];

    const int tid  = threadIdx.x;
    const int wid  = tid >> 5;
    const int lane = tid & 31;
    const int blk  = blockIdx.x;
    const int batch = blk >> 3;
    const size_t r0 = (size_t)blk * MTILE;

    for (int i = tid; i < MDIM; i += 512) {
        wq_s[i] = g_wq[batch * MDIM + i];
        v_s[i]  = vd[i];
    }

    const uint32_t bbuf0 = smem_u32(smemB);

    // ---- issue B for iters 0 and 1 (two groups; bufs 0 and 1) ----
#pragma unroll
    for (int j = 0; j < 2; j++) {
        const uint32_t dst = bbuf0 + (uint32_t)(j * SMEM_BBUF_BYTES);
#pragma unroll
        for (int it = 0; it < 2; it++) {
            int idx = tid + it * 512;
            int n = idx >> 2, kg = idx & 3;
            cp_async16(dst + (uint32_t)(n * 80 + kg * 16),
                       (const char*)g_U16 + n * 1024 + j * 64 + kg * 16);
        }
        cp_commit();
    }

    // ---- A conversion: 16 slices of 32 k; thread: row = tid>>2, 8 k at (tid&3)*8 ----
    const int arow = tid >> 2;
    const int akq  = (tid & 3) * 8;
    const float* aSrc = H + (r0 + (size_t)arow) * KDIM + akq;
    __half* aDst = smemA + arow * APAD + akq;

    float4 rA[4];   // two pending 32k slices (8 fp32 each)
    {   // prologue: store slices 0,1; load slices 2,3 into regs
#pragma unroll
        for (int sl = 0; sl < 2; sl++) {
            const float4* sp = reinterpret_cast<const float4*>(aSrc + sl * KSEG);
            float4 f0 = sp[0], f1 = sp[1];
            uint4 u;
            u.x = pack_h2(f0.x, f0.y); u.y = pack_h2(f0.z, f0.w);
            u.z = pack_h2(f1.x, f1.y); u.w = pack_h2(f1.z, f1.w);
            *reinterpret_cast<uint4*>(aDst + sl * KSEG) = u;
        }
        const float4* s2 = reinterpret_cast<const float4*>(aSrc + 2 * KSEG);
        const float4* s3 = reinterpret_cast<const float4*>(aSrc + 3 * KSEG);
        rA[0] = s2[0]; rA[1] = s2[1];
        rA[2] = s3[0]; rA[3] = s3[1];
    }

    // ---- per-lane ldmatrix addressing (R5/R9 layout) ----
    const int sub = lane >> 3;      // 8x8 tile index within x4
    const int l8  = lane & 7;
    const int rowgrp = wid >> 2;    // 4 rowgrps x 32 rows
    const int ngrp   = wid & 3;     // 4 ngrps x 64 n
    const int rbase  = rowgrp * 32;

    // A x4 tiles: t0 r0-7/k0-7, t1 r8-15/k0-7, t2 r0-7/k8-15, t3 r8-15/k8-15
    const uint32_t aAddr0 = smem_u32(smemA) +
        (uint32_t)(((rbase + (sub & 1) * 8 + l8) * APAD + (sub >> 1) * 8) * 2);
    const uint32_t aAddr1 = aAddr0 + (uint32_t)(16 * APAD * 2);
    // B x4 tiles: t0 n0-7/k0-7, t1 n0-7/k8-15, t2 n8-15/k0-7, t3 n8-15/k8-15
    const uint32_t bOff = (uint32_t)((ngrp * 64 + (sub >> 1) * 8 + l8) * 80 + (sub & 1) * 16);

    const int qn = (lane & 3) * 2;
    float s[4] = {0.0f, 0.0f, 0.0f, 0.0f};
    float acc[2][8][4];

    for (int sup = 0; sup < NSUPER; sup++) {
        const int i0 = sup * 2;
        if ((i0 & 15) == 0) {
#pragma unroll
            for (int mt = 0; mt < 2; mt++)
#pragma unroll
                for (int j = 0; j < 8; j++)
#pragma unroll
                    for (int q = 0; q < 4; q++) acc[mt][j][q] = 0.0f;
        }

        // ---- wait the 2 pending groups (issued one super-iter ago), ONE barrier ----
        cp_wait0();
        __syncthreads();
        // barrier proves compute(super-1) done -> bufs (i0+2)%4,(i0+3)%4 are free

        // ---- issue groups i0+2, i0+3 ----
#pragma unroll
        for (int dj = 2; dj < 4; dj++) {
            const int j = i0 + dj;
            if (j < NITER) {
                const int nb_g = (j >> 4) * NCHUNK;
                const int ksb  = (j & 15) * 64;
                const uint32_t dst = bbuf0 + (uint32_t)((j & 3) * SMEM_BBUF_BYTES);
#pragma unroll
                for (int it = 0; it < 2; it++) {
                    int idx = tid + it * 512;
                    int n = idx >> 2, kg = idx & 3;
                    cp_async16(dst + (uint32_t)(n * 80 + kg * 16),
                               (const char*)g_U16 + (size_t)(nb_g + n) * 1024 + ksb + kg * 16);
                }
                cp_commit();
            }
        }

        // ---- A pipeline during chunk 0: store slices 2sup+2,2sup+3; load next pair ----
        if (sup < 7) {
#pragma unroll
            for (int h = 0; h < 2; h++) {
                uint4 u;
                u.x = pack_h2(rA[h * 2].x, rA[h * 2].y);
                u.y = pack_h2(rA[h * 2].z, rA[h * 2].w);
                u.z = pack_h2(rA[h * 2 + 1].x, rA[h * 2 + 1].y);
                u.w = pack_h2(rA[h * 2 + 1].z, rA[h * 2 + 1].w);
                *reinterpret_cast<uint4*>(aDst + (2 * sup + 2 + h) * KSEG) = u;
            }
            if (sup < 6) {
                const float4* sE = reinterpret_cast<const float4*>(aSrc + (2 * sup + 4) * KSEG);
                const float4* sO = reinterpret_cast<const float4*>(aSrc + (2 * sup + 5) * KSEG);
                rA[0] = sE[0]; rA[1] = sE[1];
                rA[2] = sO[0]; rA[3] = sO[1];
            }
        }

        // ---- compute 2 iterations, no barrier between ----
#pragma unroll
        for (int ii = 0; ii < 2; ii++) {
            const int i = i0 + ii;
            const int kseg = i & 15;
            const uint32_t bA = bbuf0 + (uint32_t)((i & 3) * SMEM_BBUF_BYTES) + bOff;
            const uint32_t aK = (uint32_t)(kseg * 64);

#pragma unroll
            for (int ks = 0; ks < 2; ks++) {
                uint32_t af[2][4];
                ldsm_x4(aAddr0 + aK + ks * 32, af[0][0], af[0][1], af[0][2], af[0][3]);
                ldsm_x4(aAddr1 + aK + ks * 32, af[1][0], af[1][1], af[1][2], af[1][3]);
                uint32_t bf[4][4];
#pragma unroll
                for (int nb = 0; nb < 4; nb++)
                    ldsm_x4(bA + nb * (16 * 80) + ks * 32,
                            bf[nb][0], bf[nb][1], bf[nb][2], bf[nb][3]);
#pragma unroll
                for (int mt = 0; mt < 2; mt++)
#pragma unroll
                    for (int nb = 0; nb < 4; nb++) {
                        mma16816(acc[mt][nb * 2],     af[mt], bf[nb][0], bf[nb][1]);
                        mma16816(acc[mt][nb * 2 + 1], af[mt], bf[nb][2], bf[nb][3]);
                    }
            }

            if (kseg == 15) {
                // ---- fused epilogue for this 256-n chunk ----
                const int nbase = (i >> 4) * NCHUNK + ngrp * 64;
#pragma unroll
                for (int mt = 0; mt < 2; mt++)
#pragma unroll
                    for (int j = 0; j < 8; j++) {
                        int n = nbase + (j >> 1) * 16 + (j & 1) * 8 + qn;
                        float w0 = wq_s[n], w1 = wq_s[n + 1];
                        float v0 = v_s[n],  v1 = v_s[n + 1];
                        s[mt * 2]     = fmaf(v0, fast_tanh(w0 + acc[mt][j][0]), s[mt * 2]);
                        s[mt * 2]     = fmaf(v1, fast_tanh(w1 + acc[mt][j][1]), s[mt * 2]);
                        s[mt * 2 + 1] = fmaf(v0, fast_tanh(w0 + acc[mt][j][2]), s[mt * 2 + 1]);
                        s[mt * 2 + 1] = fmaf(v1, fast_tanh(w1 + acc[mt][j][3]), s[mt * 2 + 1]);
                    }
            }
        }
    }

    // ---- final reduction: quad shuffle + per-ngrp arrays ----
#pragma unroll
    for (int q = 0; q < 4; q++) {
        s[q] += __shfl_xor_sync(0xffffffffu, s[q], 1);
        s[q] += __shfl_xor_sync(0xffffffffu, s[q], 2);
    }
    if ((lane & 3) == 0) {
        const int rr = rbase + (lane >> 2);
        score4[ngrp][rr]      = s[0];
        score4[ngrp][rr + 8]  = s[1];
        score4[ngrp][rr + 16] = s[2];
        score4[ngrp][rr + 24] = s[3];
    }
    __syncthreads();
    if (tid < MTILE)
        out[r0 + tid] = (score4[0][tid] + score4[1][tid]) + (score4[2][tid] + score4[3][tid]);
}

// ======================= kernel 4: softmax over T, in-place =======================
__global__ void __launch_bounds__(256, 1) softmax_kernel(float* __restrict__ out) {
    __shared__ float red[256];
    float* p = out + (size_t)blockIdx.x * TLEN;
    int tid = threadIdx.x;
    float v[4];
    float m = -1e30f;
#pragma unroll
    for (int j = 0; j < 4; j++) { v[j] = p[tid + j * 256]; m = fmaxf(m, v[j]); }
    red[tid] = m; __syncthreads();
    for (int s = 128; s > 0; s >>= 1) {
        if (tid < s) red[tid] = fmaxf(red[tid], red[tid + s]);
        __syncthreads();
    }
    float mx = red[0];
    __syncthreads();
    float sum = 0.0f;
#pragma unroll
    for (int j = 0; j < 4; j++) { v[j] = __expf(v[j] - mx); sum += v[j]; }
    red[tid] = sum; __syncthreads();
    for (int s = 128; s > 0; s >>= 1) {
        if (tid < s) red[tid] += red[tid + s];
        __syncthreads();
    }
    float inv = 1.0f / red[0];
#pragma unroll
    for (int j = 0; j < 4; j++) p[tid + j * 256] = v[j] * inv;
}

// ======================= launch =======================
extern "C" void kernel_launch(void* const* d_in, const int* in_sizes, int n_in,
                              void* d_out, int out_size) {
    const float *dt = nullptr, *st = nullptr, *H = nullptr;
    const float *W = nullptr, *U = nullptr, *v = nullptr;
    int c32768 = 0, c262144 = 0;
    for (int i = 0; i < n_in; i++) {
        int s = in_sizes[i];
        if (s == 32768)          { if (c32768++ == 0) dt = (const float*)d_in[i]; else st = (const float*)d_in[i]; }
        else if (s == 67108864)  { H = (const float*)d_in[i]; }
        else if (s == 262144)    { if (c262144++ == 0) W = (const float*)d_in[i]; else U = (const float*)d_in[i]; }
        else if (s == 512)       { v = (const float*)d_in[i]; }
    }
    float* out = (float*)d_out;

    cudaFuncSetAttribute(attn_gemm_kernel, cudaFuncAttributeMaxDynamicSharedMemorySize, DYN_SMEM);

    pack_kernel<<<256, 256>>>(dt, st, U);      // abs idx 2
    wq_kernel<<<64, 128>>>(W);                 // 3
    dummy_kernel<<<1, 32>>>();                 // 4
    attn_gemm_kernel<<<1024, 512, DYN_SMEM>>>(H, v, out);   // 5 <- ncu -s 5
    softmax_kernel<<<128, 256>>>(out);
}